// round 1
// baseline (speedup 1.0000x reference)
#include <cuda_runtime.h>
#include <cuda_bf16.h>

// Problem constants (fixed shapes for this problem instance)
#define NNODE 2048
#define NLOG  11              // log2(NNODE)
#define NN    (NNODE * NNODE) // 4M positions per head
#define NHEAD 8

// Scratch: winner[p] holds (edge_index + 1) of the last (max-index) edge that
// targets position p, or 0 if empty. Zero-initialized at module load; the fill
// kernel resets it to 0 after consuming it, so every kernel_launch (and every
// graph replay) starts from the empty state -> deterministic.
__device__ int g_winner[NN];
__device__ int g_is64;

// Detect whether edge_index is stored as int64 (reference declares int64, but
// jax without x64 canonicalizes to int32). If the data is int64 with values in
// [0, 2048), every odd 32-bit word is 0. If it's int32, the odd words are
// random node ids — the probability of 256 consecutive zeros is ~(1/2048)^256.
__global__ void detect_kernel(const int* __restrict__ idx32) {
    if (blockIdx.x == 0 && threadIdx.x == 0) {
        int o = 0;
#pragma unroll
        for (int i = 0; i < 256; i++) o |= idx32[2 * i + 1];
        g_is64 = (o == 0) ? 1 : 0;
    }
}

// Pass 2: per-edge atomicMax into the winner map (L2-resident, 16 MB).
__global__ void scatter_max_kernel(const void* __restrict__ eidx, int E) {
    int e = blockIdx.x * blockDim.x + threadIdx.x;
    if (e >= E) return;
    int row, col;
    if (g_is64) {
        const long long* p = (const long long*)eidx;
        row = (int)p[e];
        col = (int)p[(size_t)E + e];
    } else {
        const int* p = (const int*)eidx;
        row = p[e];
        col = p[E + e];
    }
    atomicMax(&g_winner[(row << NLOG) + col], e + 1);
}

// Pass 3: one thread per 4 consecutive positions. Reads+resets winner,
// computes the 3->8 linear + sigmoid only at occupied positions (~6%), and
// writes all 8 head-planes with coalesced float4 stores. Covers every output
// element (d_out is poisoned by the harness).
__global__ void fill_kernel(const float* __restrict__ score,
                            const float* __restrict__ W,
                            const float* __restrict__ b,
                            float* __restrict__ out) {
    int t  = blockIdx.x * blockDim.x + threadIdx.x;
    int p4 = t << 2;

    int4 w = *(const int4*)(g_winner + p4);
    *(int4*)(g_winner + p4) = make_int4(0, 0, 0, 0);

    float v[NHEAD][4];
#pragma unroll
    for (int h = 0; h < NHEAD; h++) {
        v[h][0] = 0.f; v[h][1] = 0.f; v[h][2] = 0.f; v[h][3] = 0.f;
    }

    int ws[4] = {w.x, w.y, w.z, w.w};
    if (w.x | w.y | w.z | w.w) {
#pragma unroll
        for (int j = 0; j < 4; j++) {
            int wj = ws[j];
            if (wj != 0) {
                int   e  = wj - 1;
                float s  = score[e];
                int   p  = p4 + j;
                float fr = (float)(p >> NLOG);
                float fc = (float)(p & (NNODE - 1));
#pragma unroll
                for (int h = 0; h < NHEAD; h++) {
                    float x = fmaf(W[3 * h], fr,
                              fmaf(W[3 * h + 1], fc,
                              fmaf(W[3 * h + 2], s, b[h])));
                    // sigmoid; saturates to exact 0/1 for large |x|, matching ref
                    v[h][j] = 1.f / (1.f + __expf(-x));
                }
            }
        }
    }

#pragma unroll
    for (int h = 0; h < NHEAD; h++) {
        float4 o4 = make_float4(v[h][0], v[h][1], v[h][2], v[h][3]);
        *(float4*)(out + (size_t)h * NN + p4) = o4;
    }
}

extern "C" void kernel_launch(void* const* d_in, const int* in_sizes, int n_in,
                              void* d_out, int out_size) {
    // metadata order: edge_index, edge_score, W, b, num_nodes
    const void*  eidx  = d_in[0];
    const float* score = (const float*)d_in[1];
    const float* W     = (const float*)d_in[2];
    const float* b     = (const float*)d_in[3];
    float*       out   = (float*)d_out;

    int E = in_sizes[1]; // edge_score has E elements

    detect_kernel<<<1, 32>>>((const int*)eidx);
    scatter_max_kernel<<<(E + 255) / 256, 256>>>(eidx, E);
    fill_kernel<<<NN / 4 / 256, 256>>>(score, W, b, out);
}

// round 2
// speedup vs baseline: 1.5405x; 1.5405x over previous
#include <cuda_runtime.h>
#include <cuda_bf16.h>

// Problem constants (fixed shapes for this problem instance)
#define NNODE 2048
#define NLOG  11              // log2(NNODE)
#define NN    (NNODE * NNODE) // 4M positions per head
#define NHEAD 8

// Scratch: winner[p] holds (edge_index + 1) of the max-index (== last-applied,
// matching XLA scatter ordering) edge targeting position p, or 0 if empty.
// Zero at module load; fill resets it after consuming -> every replay starts
// from the empty state (deterministic).
__device__ int g_winner[NN];

// Pass 1: per-edge atomicMax into the winner map (16 MB, L2-resident).
// Layout detection (int64 vs jax-canonicalized int32) is done per-warp with a
// ballot on the high 32-bit words: exactly zero for int64 (values < 2048),
// ~uniform node ids for int32 (P(all 32 zero) = 2048^-32 ~ 0).
__global__ void scatter_max_kernel(const void* __restrict__ eidx, int E) {
    int e = blockIdx.x * blockDim.x + threadIdx.x;
    bool valid = (e < E);
    int ec = valid ? e : 0;

    // Speculative 64-bit load: word pair (2e, 2e+1). In-bounds in both layouts.
    long long v64 = ((const long long*)eidx)[ec];
    int hi = (int)(v64 >> 32);
    unsigned any32 = __ballot_sync(0xffffffffu, hi != 0);

    int row, col;
    if (any32 == 0) {           // int64 layout
        row = (int)v64;
        col = (int)((const long long*)eidx)[(size_t)E + ec];
    } else {                    // int32 layout
        const int* p = (const int*)eidx;
        row = p[ec];
        col = p[E + ec];
    }
    if (valid) atomicMax(&g_winner[(row << NLOG) + col], e + 1);
}

// Pass 2: one thread per 8 consecutive positions (2 x int4 winner tiles).
// Reads+resets winner with streaming hints, computes the 3->8 linear + sigmoid
// only at occupied positions (~6%), writes all 8 head-planes with coalesced
// streaming float4 stores. Covers every output element (d_out is poisoned).
__global__ void fill_kernel(const float* __restrict__ score,
                            const float* __restrict__ W,
                            const float* __restrict__ b,
                            float* __restrict__ out) {
    int t  = blockIdx.x * blockDim.x + threadIdx.x;
    int p8 = t << 3;

    int4 w0 = __ldcs((const int4*)(g_winner + p8));
    int4 w1 = __ldcs((const int4*)(g_winner + p8 + 4));
    __stcs((int4*)(g_winner + p8),     make_int4(0, 0, 0, 0));
    __stcs((int4*)(g_winner + p8 + 4), make_int4(0, 0, 0, 0));

    // Hoist weights (L1-resident broadcasts)
    float w_r[NHEAD], w_c[NHEAD], w_s[NHEAD], bb[NHEAD];
#pragma unroll
    for (int h = 0; h < NHEAD; h++) {
        w_r[h] = W[3 * h];
        w_c[h] = W[3 * h + 1];
        w_s[h] = W[3 * h + 2];
        bb[h]  = b[h];
    }

    float v[NHEAD][8];
#pragma unroll
    for (int h = 0; h < NHEAD; h++)
#pragma unroll
        for (int j = 0; j < 8; j++) v[h][j] = 0.f;

    int ws[8] = {w0.x, w0.y, w0.z, w0.w, w1.x, w1.y, w1.z, w1.w};
    int occ = (w0.x | w0.y | w0.z | w0.w | w1.x | w1.y | w1.z | w1.w);
    if (occ) {
#pragma unroll
        for (int j = 0; j < 8; j++) {
            int wj = ws[j];
            if (wj != 0) {
                int   e  = wj - 1;
                float s  = score[e];
                int   p  = p8 + j;
                float fr = (float)(p >> NLOG);
                float fc = (float)(p & (NNODE - 1));
#pragma unroll
                for (int h = 0; h < NHEAD; h++) {
                    float x = fmaf(w_r[h], fr,
                              fmaf(w_c[h], fc,
                              fmaf(w_s[h], s, bb[h])));
                    // sigmoid; saturates to exact 0/1 for large |x| like ref
                    v[h][j] = __fdividef(1.f, 1.f + __expf(-x));
                }
            }
        }
    }

#pragma unroll
    for (int h = 0; h < NHEAD; h++) {
        float* base = out + (size_t)h * NN + p8;
        __stcs((float4*)base,       make_float4(v[h][0], v[h][1], v[h][2], v[h][3]));
        __stcs((float4*)(base + 4), make_float4(v[h][4], v[h][5], v[h][6], v[h][7]));
    }
}

extern "C" void kernel_launch(void* const* d_in, const int* in_sizes, int n_in,
                              void* d_out, int out_size) {
    // metadata order: edge_index, edge_score, W, b, num_nodes
    const void*  eidx  = d_in[0];
    const float* score = (const float*)d_in[1];
    const float* W     = (const float*)d_in[2];
    const float* b     = (const float*)d_in[3];
    float*       out   = (float*)d_out;

    int E = in_sizes[1]; // edge_score has E elements

    scatter_max_kernel<<<(E + 255) / 256, 256>>>(eidx, E);
    fill_kernel<<<NN / 8 / 256, 256>>>(score, W, b, out);
}

// round 4
// speedup vs baseline: 2.5654x; 1.6653x over previous
#include <cuda_runtime.h>
#include <cuda_bf16.h>

// Problem constants (fixed shapes for this problem instance)
#define NNODE 2048
#define NLOG  11              // log2(NNODE)
#define NN    (NNODE * NNODE) // 4M positions per head
#define NHEAD 8

// winner[p] = (edge_index + 1) of the max-index (last-applied, matching XLA
// scatter ordering) edge targeting position p, or 0 if empty. Zero at module
// load; fill resets after consuming -> every graph replay starts empty.
__device__ int g_winner[NN];

// Pass 1: per-edge atomicMax into the winner map (16 MB, L2-resident).
// Layout detection (int64 vs jax-canonicalized int32) via per-warp ballot on
// the high 32-bit words: all-zero for int64 (values < 2048), ~random for int32.
__global__ void scatter_max_kernel(const void* __restrict__ eidx, int E) {
    int e = blockIdx.x * blockDim.x + threadIdx.x;
    bool valid = (e < E);
    int ec = valid ? e : 0;

    long long v64 = ((const long long*)eidx)[ec]; // in-bounds in both layouts
    int hi = (int)(v64 >> 32);
    unsigned any32 = __ballot_sync(0xffffffffu, hi != 0);

    int row, col;
    if (any32 == 0) {           // int64 layout
        row = (int)v64;
        col = (int)((const long long*)eidx)[(size_t)E + ec];
    } else {                    // int32 layout
        const int* p = (const int*)eidx;
        row = p[ec];
        col = p[E + ec];
    }
    if (valid) atomicMax(&g_winner[(row << NLOG) + col], e + 1);
}

// Pass 2: one thread per 8 consecutive positions (all in the same output row).
// Head-major outer loop (unroll 1) keeps live registers low -> high occupancy.
// Streaming loads/stores keep the 128 MB output from thrashing L2.
__global__ void __launch_bounds__(256) fill_kernel(
        const float* __restrict__ score,
        const float* __restrict__ W,
        const float* __restrict__ b,
        float* __restrict__ out) {
    int t  = blockIdx.x * blockDim.x + threadIdx.x;
    int p8 = t << 3;

    int4 w0 = __ldcs((const int4*)(g_winner + p8));
    int4 w1 = __ldcs((const int4*)(g_winner + p8 + 4));
    __stcs((int4*)(g_winner + p8),     make_int4(0, 0, 0, 0));
    __stcs((int4*)(g_winner + p8 + 4), make_int4(0, 0, 0, 0));

    int ws[8] = {w0.x, w0.y, w0.z, w0.w, w1.x, w1.y, w1.z, w1.w};
    int occ = (w0.x | w0.y | w0.z | w0.w | w1.x | w1.y | w1.z | w1.w);

    // All 8 positions share one row; cols are fc0..fc0+7.
    float fr  = (float)(p8 >> NLOG);
    float fc0 = (float)(p8 & (NNODE - 1));

    // Gather scores once (only occupied lanes issue loads).
    float s[8];
    if (occ) {
#pragma unroll
        for (int j = 0; j < 8; j++)
            s[j] = ws[j] ? __ldg(&score[ws[j] - 1]) : 0.f;
    }

#pragma unroll 1
    for (int h = 0; h < NHEAD; h++) {
        float4 lo = make_float4(0.f, 0.f, 0.f, 0.f);
        float4 hi4 = make_float4(0.f, 0.f, 0.f, 0.f);
        if (occ) {
            float wr  = __ldg(&W[3 * h]);
            float wc  = __ldg(&W[3 * h + 1]);
            float wsc = __ldg(&W[3 * h + 2]);
            float A   = fmaf(wc, fc0, fmaf(wr, fr, __ldg(&b[h])));
            float v[8];
#pragma unroll
            for (int j = 0; j < 8; j++) {
                if (ws[j]) {
                    float x = fmaf(wsc, s[j], fmaf(wc, (float)j, A));
                    v[j] = __fdividef(1.f, 1.f + __expf(-x)); // saturates to 0/1 like ref
                } else {
                    v[j] = 0.f;
                }
            }
            lo  = make_float4(v[0], v[1], v[2], v[3]);
            hi4 = make_float4(v[4], v[5], v[6], v[7]);
        }
        float* base = out + (size_t)h * NN + p8;
        __stcs((float4*)base,       lo);
        __stcs((float4*)(base + 4), hi4);
    }
}

extern "C" void kernel_launch(void* const* d_in, const int* in_sizes, int n_in,
                              void* d_out, int out_size) {
    // metadata order: edge_index, edge_score, W, b, num_nodes
    const void*  eidx  = d_in[0];
    const float* score = (const float*)d_in[1];
    const float* W     = (const float*)d_in[2];
    const float* b     = (const float*)d_in[3];
    float*       out   = (float*)d_out;

    int E = in_sizes[1]; // edge_score has E elements

    scatter_max_kernel<<<(E + 255) / 256, 256>>>(eidx, E);
    fill_kernel<<<NN / 8 / 256, 256>>>(score, W, b, out);
}

// round 7
// speedup vs baseline: 3.0000x; 1.1694x over previous
#include <cuda_runtime.h>
#include <cuda_bf16.h>

// Problem constants (fixed shapes for this problem instance)
#define NNODE 2048
#define NLOG  11              // log2(NNODE)
#define NN    (NNODE * NNODE) // 4M positions per head
#define NHEAD 8

// winner[p] = (edge_index + 1) of the max-index (last-applied, matching XLA
// scatter ordering) edge targeting position p, or 0 if empty. Zero at module
// load; fill resets occupied groups after consuming (empty groups are never
// dirtied) -> every graph replay starts from the all-zero state.
__device__ int g_winner[NN];

// Pass 1: per-edge atomicMax into the winner map (16 MB, L2-resident).
// Layout detection (int64 vs jax-canonicalized int32) via per-warp ballot on
// the high 32-bit words: all-zero for int64 (values < 2048), ~random for int32.
__global__ void scatter_max_kernel(const void* __restrict__ eidx, int E) {
    int e = blockIdx.x * blockDim.x + threadIdx.x;
    bool valid = (e < E);
    int ec = valid ? e : 0;

    long long v64 = ((const long long*)eidx)[ec]; // in-bounds in both layouts
    int hi = (int)(v64 >> 32);
    unsigned any32 = __ballot_sync(0xffffffffu, hi != 0);

    int row, col;
    if (any32 == 0) {           // int64 layout
        row = (int)v64;
        col = (int)((const long long*)eidx)[(size_t)E + ec];
    } else {                    // int32 layout
        const int* p = (const int*)eidx;
        row = p[ec];
        col = p[E + ec];
    }
    if (valid) atomicMax(&g_winner[(row << NLOG) + col], e + 1);
}

// 256-bit vector memory ops (sm_100a). All addresses are 32B-aligned.
__device__ __forceinline__ void ldg_v8_u32(const int* p, unsigned w[8]) {
    asm volatile("ld.global.cs.v8.u32 {%0,%1,%2,%3,%4,%5,%6,%7}, [%8];"
                 : "=r"(w[0]), "=r"(w[1]), "=r"(w[2]), "=r"(w[3]),
                   "=r"(w[4]), "=r"(w[5]), "=r"(w[6]), "=r"(w[7])
                 : "l"(p));
}
__device__ __forceinline__ void stg_v8_zero_u32(int* p) {
    asm volatile("st.global.cs.v8.u32 [%0], {%1,%1,%1,%1,%1,%1,%1,%1};"
                 :: "l"(p), "r"(0u) : "memory");
}
__device__ __forceinline__ void stg_v8_f32(float* p, const float v[8]) {
    asm volatile("st.global.cs.v8.f32 [%0], {%1,%2,%3,%4,%5,%6,%7,%8};"
                 :: "l"(p), "f"(v[0]), "f"(v[1]), "f"(v[2]), "f"(v[3]),
                    "f"(v[4]), "f"(v[5]), "f"(v[6]), "f"(v[7])
                 : "memory");
}

// Pass 2: one thread per 8 consecutive positions (same output row).
// Winner group in one v8 load; occupied threads reset their group (v8 zero
// store) and gather scores; all threads emit 8 v8 output stores (one per head).
// Weights live in registers via 8 broadcast float4 loads; head loop fully
// unrolled so weight indexing is constant.
__global__ void __launch_bounds__(256) fill_kernel(
        const float* __restrict__ score,
        const float* __restrict__ W,
        const float* __restrict__ b,
        float* __restrict__ out) {
    int t  = blockIdx.x * blockDim.x + threadIdx.x;
    int p8 = t << 3;

    unsigned ws[8];
    ldg_v8_u32(g_winner + p8, ws);
    unsigned occ = ws[0] | ws[1] | ws[2] | ws[3] | ws[4] | ws[5] | ws[6] | ws[7];

    // Weights -> registers (8 LDG.128 broadcasts per warp).
    const float4* W4 = (const float4*)W;
    float4 q0 = __ldg(W4 + 0), q1 = __ldg(W4 + 1), q2 = __ldg(W4 + 2);
    float4 q3 = __ldg(W4 + 3), q4 = __ldg(W4 + 4), q5 = __ldg(W4 + 5);
    float4 qb0 = __ldg((const float4*)b), qb1 = __ldg((const float4*)b + 1);
    float wf[24] = {q0.x, q0.y, q0.z, q0.w, q1.x, q1.y, q1.z, q1.w,
                    q2.x, q2.y, q2.z, q2.w, q3.x, q3.y, q3.z, q3.w,
                    q4.x, q4.y, q4.z, q4.w, q5.x, q5.y, q5.z, q5.w};
    float bf[8]  = {qb0.x, qb0.y, qb0.z, qb0.w, qb1.x, qb1.y, qb1.z, qb1.w};

    // All 8 positions share one row; cols are fc0..fc0+7.
    float fr  = (float)(p8 >> NLOG);
    float fc0 = (float)(p8 & (NNODE - 1));

    float s[8];
#pragma unroll
    for (int j = 0; j < 8; j++) s[j] = 0.f;

    if (occ) {
        stg_v8_zero_u32(g_winner + p8); // consume + reset (replay determinism)
#pragma unroll
        for (int j = 0; j < 8; j++)
            if (ws[j]) s[j] = __ldg(&score[ws[j] - 1]);
    }

#pragma unroll
    for (int h = 0; h < NHEAD; h++) {
        float wr  = wf[3 * h];
        float wc  = wf[3 * h + 1];
        float wsc = wf[3 * h + 2];
        float A   = fmaf(wc, fc0, fmaf(wr, fr, bf[h]));
        float v[8];
#pragma unroll
        for (int j = 0; j < 8; j++) {
            if (ws[j]) {
                float x = fmaf(wsc, s[j], fmaf(wc, (float)j, A));
                v[j] = __fdividef(1.f, 1.f + __expf(-x)); // saturates to 0/1 like ref
            } else {
                v[j] = 0.f;
            }
        }
        stg_v8_f32(out + (size_t)h * NN + p8, v);
    }
}

extern "C" void kernel_launch(void* const* d_in, const int* in_sizes, int n_in,
                              void* d_out, int out_size) {
    // metadata order: edge_index, edge_score, W, b, num_nodes
    const void*  eidx  = d_in[0];
    const float* score = (const float*)d_in[1];
    const float* W     = (const float*)d_in[2];
    const float* b     = (const float*)d_in[3];
    float*       out   = (float*)d_out;

    int E = in_sizes[1]; // edge_score has E elements

    scatter_max_kernel<<<(E + 255) / 256, 256>>>(eidx, E);
    fill_kernel<<<NN / 8 / 256, 256>>>(score, W, b, out);
}

// round 8
// speedup vs baseline: 3.3134x; 1.1045x over previous
#include <cuda_runtime.h>
#include <cuda_bf16.h>

// Problem constants (fixed shapes for this problem instance)
#define NNODE 2048
#define NLOG  11              // log2(NNODE)
#define NN    (NNODE * NNODE) // 4M positions per head
#define NHEAD 8

// winner[p] = (edge_index + 1) of the max-index (last-applied, matching XLA
// scatter ordering) edge targeting position p, or 0 if empty. Zero at module
// load; fill resets occupied groups after consuming (empty groups are never
// dirtied) -> every graph replay starts from the all-zero state.
__device__ int g_winner[NN];

// Pass 1: 4 edges per thread, atomicMax (RED.MAX, no return) into the winner
// map (16 MB, L2-resident). Layout detection (int64 vs jax-canonicalized
// int32) via per-warp ballot on would-be int64 high words.
__global__ void scatter_max_kernel(const void* __restrict__ eidx, int E) {
    int t  = blockIdx.x * blockDim.x + threadIdx.x;
    int e4 = t << 2;
    if (e4 >= E) return;

    // Probe load: int4 at index 2t == rows[e4..e4+1] if int64. In-bounds in
    // both layouts. int64 => .y/.w are high words == 0 (values < 2048).
    int4 a = ((const int4*)eidx)[2 * t];
    unsigned any32 = __ballot_sync(0xffffffffu, (a.y | a.w) != 0);

    int rows[4], cols[4];
    if (any32 == 0) {           // int64 layout
        int4 a2 = ((const int4*)eidx)[2 * t + 1];
        int4 c1 = ((const int4*)eidx)[(size_t)(E >> 1) + 2 * t];
        int4 c2 = ((const int4*)eidx)[(size_t)(E >> 1) + 2 * t + 1];
        rows[0] = a.x;  rows[1] = a.z;  rows[2] = a2.x; rows[3] = a2.z;
        cols[0] = c1.x; cols[1] = c1.z; cols[2] = c2.x; cols[3] = c2.z;
    } else {                    // int32 layout
        int4 r = ((const int4*)eidx)[t];
        int4 c = ((const int4*)eidx)[(size_t)(E >> 2) + t];
        rows[0] = r.x; rows[1] = r.y; rows[2] = r.z; rows[3] = r.w;
        cols[0] = c.x; cols[1] = c.y; cols[2] = c.z; cols[3] = c.w;
    }
#pragma unroll
    for (int k = 0; k < 4; k++) {
        int e = e4 + k;
        if (e < E)
            atomicMax(&g_winner[(rows[k] << NLOG) + cols[k]], e + 1);
    }
}

// 256-bit vector memory ops (sm_100a). All addresses are 32B-aligned.
__device__ __forceinline__ void ldg_v8_u32(const int* p, unsigned w[8]) {
    asm volatile("ld.global.cs.v8.u32 {%0,%1,%2,%3,%4,%5,%6,%7}, [%8];"
                 : "=r"(w[0]), "=r"(w[1]), "=r"(w[2]), "=r"(w[3]),
                   "=r"(w[4]), "=r"(w[5]), "=r"(w[6]), "=r"(w[7])
                 : "l"(p));
}
__device__ __forceinline__ void stg_v8_zero_u32(int* p) {
    asm volatile("st.global.cs.v8.u32 [%0], {%1,%1,%1,%1,%1,%1,%1,%1};"
                 :: "l"(p), "r"(0u) : "memory");
}
__device__ __forceinline__ void stg_v8_f32(float* p, const float v[8]) {
    asm volatile("st.global.cs.v8.f32 [%0], {%1,%2,%3,%4,%5,%6,%7,%8};"
                 :: "l"(p), "f"(v[0]), "f"(v[1]), "f"(v[2]), "f"(v[3]),
                    "f"(v[4]), "f"(v[5]), "f"(v[6]), "f"(v[7])
                 : "memory");
}

// Fast sigmoid: 1 MUFU (tanh.approx) + 2 FMA-pipe ops. Saturates to exact 0/1
// for large |x|, matching the fp32 reference; approx error (~1e-3 abs) only in
// the narrow transition band.
__device__ __forceinline__ float fast_sigmoid(float x) {
    float t;
    asm("tanh.approx.f32 %0, %1;" : "=f"(t) : "f"(0.5f * x));
    return fmaf(0.5f, t, 0.5f);
}

// Pass 2: one thread per 8 consecutive positions (same output row).
// Head-major loop (unroll 1) with shared-memory weights keeps live registers
// low -> high occupancy; v8 streaming loads/stores halve the memory
// instruction stream. Covers every output element (d_out is poisoned).
__global__ void __launch_bounds__(256) fill_kernel(
        const float* __restrict__ score,
        const float* __restrict__ W,
        const float* __restrict__ b,
        float* __restrict__ out) {
    __shared__ float sW[3 * NHEAD];
    __shared__ float sb[NHEAD];
    if (threadIdx.x < 3 * NHEAD) sW[threadIdx.x] = W[threadIdx.x];
    if (threadIdx.x < NHEAD)     sb[threadIdx.x] = b[threadIdx.x];
    __syncthreads();

    int t  = blockIdx.x * blockDim.x + threadIdx.x;
    int p8 = t << 3;

    unsigned ws[8];
    ldg_v8_u32(g_winner + p8, ws);
    unsigned occ = ws[0] | ws[1] | ws[2] | ws[3] | ws[4] | ws[5] | ws[6] | ws[7];

    // All 8 positions share one row; cols are fc0..fc0+7.
    float fr  = (float)(p8 >> NLOG);
    float fc0 = (float)(p8 & (NNODE - 1));

    float s[8];
#pragma unroll
    for (int j = 0; j < 8; j++) s[j] = 0.f;

    if (occ) {
        stg_v8_zero_u32(g_winner + p8); // consume + reset (replay determinism)
#pragma unroll
        for (int j = 0; j < 8; j++)
            if (ws[j]) s[j] = __ldg(&score[ws[j] - 1]);
    }

#pragma unroll 1
    for (int h = 0; h < NHEAD; h++) {
        float wr  = sW[3 * h];
        float wc  = sW[3 * h + 1];
        float wsc = sW[3 * h + 2];
        float A   = fmaf(wc, fc0, fmaf(wr, fr, sb[h]));
        float v[8];
#pragma unroll
        for (int j = 0; j < 8; j++) {
            float x = fmaf(wsc, s[j], fmaf(wc, (float)j, A));
            v[j] = ws[j] ? fast_sigmoid(x) : 0.f;
        }
        stg_v8_f32(out + ((size_t)h << (2 * NLOG)) + p8, v);
    }
}

extern "C" void kernel_launch(void* const* d_in, const int* in_sizes, int n_in,
                              void* d_out, int out_size) {
    // metadata order: edge_index, edge_score, W, b, num_nodes
    const void*  eidx  = d_in[0];
    const float* score = (const float*)d_in[1];
    const float* W     = (const float*)d_in[2];
    const float* b     = (const float*)d_in[3];
    float*       out   = (float*)d_out;

    int E = in_sizes[1]; // edge_score has E elements

    int nt4 = (E + 3) / 4;
    scatter_max_kernel<<<(nt4 + 255) / 256, 256>>>(eidx, E);
    fill_kernel<<<NN / 8 / 256, 256>>>(score, W, b, out);
}